// round 6
// baseline (speedup 1.0000x reference)
#include <cuda_runtime.h>
#include <cuda_bf16.h>
#include <cstdint>

#define ULL unsigned long long

// ---------------------------------------------------------------------------
// Packed f32x2 helpers (sm_100+ PTX). Weights are dup-packed {w,w} once,
// activations pair-packed {row_a, row_b}; one FFMA2 = 2 fp32 FMAs.
// ---------------------------------------------------------------------------
__device__ __forceinline__ ULL dup2(float v) {
    ULL r; asm("mov.b64 %0, {%1, %1};" : "=l"(r) : "f"(v)); return r;
}
__device__ __forceinline__ ULL pk2(float lo, float hi) {
    ULL r; asm("mov.b64 %0, {%1, %2};" : "=l"(r) : "f"(lo), "f"(hi)); return r;
}
__device__ __forceinline__ void fma2(ULL& d, ULL a, ULL b) {
    asm("fma.rn.f32x2 %0, %1, %2, %0;" : "+l"(d) : "l"(a), "l"(b));
}
__device__ __forceinline__ void add2(ULL& d, ULL a) {
    asm("add.rn.f32x2 %0, %0, %1;" : "+l"(d) : "l"(a));
}
__device__ __forceinline__ void unpk(ULL v, float& lo, float& hi) {
    asm("mov.b64 {%0, %1}, %2;" : "=f"(lo), "=f"(hi) : "l"(v));
}

// Fast activations: MUFU.EX2 + MUFU.RCP based, ~2^-21 rel err, no NaN at extremes.
__device__ __forceinline__ float sig_f(float x) {
    return __fdividef(1.0f, 1.0f + __expf(-x));
}
__device__ __forceinline__ float tanh_f(float x) {
    return __fdividef(2.0f, 1.0f + __expf(-2.0f * x)) - 1.0f;
}

// ---------------------------------------------------------------------------
// Problem constants
// ---------------------------------------------------------------------------
static constexpr int B  = 1024;
static constexpr int T  = 512;
static constexpr int H  = 64;     // hidden
static constexpr int G4 = 256;    // 4*H gates
static constexpr int NB = 4;      // batch rows per CTA

// Scratch (static device arrays: allocation-free per harness rules)
__device__ float g_y0[(size_t)B * T * 128];   // layer-0 output, [b][t][dir*64 + k] (256 MB)
__device__ float g_hcat[(size_t)B * 128];     // final hidden state [hT_f, hT_b]

// ---------------------------------------------------------------------------
// Kernel 1: layer-0 bidirectional LSTM.
// grid = (B/NB, 2 dirs), block = 256. Thread j owns gate row j.
// Weights (Wih 3 + Whh 64) dup-packed in registers. h pair-interleaved in smem.
// ---------------------------------------------------------------------------
__global__ void __launch_bounds__(256, 1) lstm0_kernel(
    const float* __restrict__ x,
    const float* __restrict__ WihF, const float* __restrict__ WhhF,
    const float* __restrict__ bihF, const float* __restrict__ bhhF,
    const float* __restrict__ WihB, const float* __restrict__ WhhB,
    const float* __restrict__ bihB, const float* __restrict__ bhhB)
{
    const int dir = blockIdx.y;
    const int b0  = blockIdx.x * NB;
    const int j   = threadIdx.x;

    const float* Wih = dir ? WihB : WihF;
    const float* Whh = dir ? WhhB : WhhF;
    const float  bias = dir ? (bihB[j] + bhhB[j]) : (bihF[j] + bhhF[j]);
    const ULL bias2 = dup2(bias);

    ULL wih2[3];
    #pragma unroll
    for (int c = 0; c < 3; c++) wih2[c] = dup2(Wih[j * 3 + c]);
    ULL whh2[64];
    #pragma unroll
    for (int k = 0; k < 64; k++) whh2[k] = dup2(Whh[j * 64 + k]);

    __shared__ ulonglong2 h_pp[64];      // h_pp[k] = {(r0,r1),(r2,r3)}
    __shared__ float      g_s[NB][G4];   // activated gates

    const int r = j >> 6;        // phase-2 role: row
    const int k = j & 63;        //               hidden index
    float c_state = 0.0f;
    float hn      = 0.0f;
    const int dof = dir ? 64 : 0;
    const float* xb = x + (size_t)b0 * (3 * T);

    if (j < 64) h_pp[j] = make_ulonglong2(0ULL, 0ULL);
    __syncthreads();

    for (int s = 0; s < T; s++) {
        const int t = dir ? (T - 1 - s) : s;

        // ---- phase 1: gate pre-activations for 4 rows (2 packed pairs) ----
        ULL a0 = bias2, a1 = bias2, a0b = 0ULL, a1b = 0ULL;
        #pragma unroll
        for (int c = 0; c < 3; c++) {
            float x0 = __ldg(xb + 0 * (3 * T) + c * T + t);
            float x1 = __ldg(xb + 1 * (3 * T) + c * T + t);
            float x2 = __ldg(xb + 2 * (3 * T) + c * T + t);
            float x3 = __ldg(xb + 3 * (3 * T) + c * T + t);
            fma2(a0, wih2[c], pk2(x0, x1));
            fma2(a1, wih2[c], pk2(x2, x3));
        }
        #pragma unroll
        for (int kk = 0; kk < 64; kk += 2) {
            ulonglong2 h0 = h_pp[kk];
            ulonglong2 h1 = h_pp[kk + 1];
            fma2(a0,  whh2[kk],     h0.x);
            fma2(a1,  whh2[kk],     h0.y);
            fma2(a0b, whh2[kk + 1], h1.x);
            fma2(a1b, whh2[kk + 1], h1.y);
        }
        add2(a0, a0b);
        add2(a1, a1b);

        float v0, v1, v2, v3;
        unpk(a0, v0, v1);
        unpk(a1, v2, v3);
        if ((j >> 6) == 2) {   // g gate -> tanh
            v0 = tanh_f(v0); v1 = tanh_f(v1); v2 = tanh_f(v2); v3 = tanh_f(v3);
        } else {               // i, f, o -> sigmoid
            v0 = sig_f(v0);  v1 = sig_f(v1);  v2 = sig_f(v2);  v3 = sig_f(v3);
        }
        g_s[0][j] = v0; g_s[1][j] = v1; g_s[2][j] = v2; g_s[3][j] = v3;
        __syncthreads();

        // ---- phase 2: state update, thread -> (row r, hidden k) ----
        float ig = g_s[r][k];
        float fg = g_s[r][64 + k];
        float gg = g_s[r][128 + k];
        float og = g_s[r][192 + k];
        c_state = fg * c_state + ig * gg;
        hn = og * tanh_f(c_state);
        ((float*)&h_pp[k])[r] = hn;
        g_y0[((size_t)(b0 + r)) * (T * 128) + (size_t)t * 128 + dof + k] = hn;
        __syncthreads();
    }
}

// ---------------------------------------------------------------------------
// Kernel 2: layer-1 bidirectional LSTM with the input GEMM (K=128) FUSED.
// Wih1 (256x128) lives in padded shared (conflict-free float4 reads),
// Whh1 dup-packed in registers. Only the final hT is written.
// ---------------------------------------------------------------------------
static constexpr int WPAD = 132;                       // 128 + 4 pad (16B aligned rows)
static constexpr int WS_BYTES = G4 * WPAD * 4;         // 135168
static constexpr int Y_OFF = WS_BYTES;                 // ulonglong2 y_pp[128]
static constexpr int H_OFF = Y_OFF + 128 * 16;         // ulonglong2 h_pp[64]
static constexpr int GS_OFF = H_OFF + 64 * 16;         // float g_s[4][256]
static constexpr int SMEM1 = GS_OFF + NB * G4 * 4;     // 142336 bytes

__global__ void __launch_bounds__(256, 1) lstm1_kernel(
    const float* __restrict__ WihF, const float* __restrict__ WhhF,
    const float* __restrict__ bihF, const float* __restrict__ bhhF,
    const float* __restrict__ WihB, const float* __restrict__ WhhB,
    const float* __restrict__ bihB, const float* __restrict__ bhhB)
{
    extern __shared__ char sm[];
    float*      ws   = (float*)sm;
    ulonglong2* y_pp = (ulonglong2*)(sm + Y_OFF);
    ulonglong2* h_pp = (ulonglong2*)(sm + H_OFF);
    float (*g_s)[G4] = (float (*)[G4])(sm + GS_OFF);

    const int dir = blockIdx.y;
    const int b0  = blockIdx.x * NB;
    const int j   = threadIdx.x;

    const float* Wih = dir ? WihB : WihF;
    const float* Whh = dir ? WhhB : WhhF;
    const float  bias = dir ? (bihB[j] + bhhB[j]) : (bihF[j] + bhhF[j]);
    const ULL bias2 = dup2(bias);

    // stage Wih1 into padded shared (coalesced)
    for (int idx = j; idx < G4 * 128; idx += 256) {
        int row = idx >> 7, kk = idx & 127;
        ws[row * WPAD + kk] = Wih[idx];
    }
    ULL whh2[64];
    #pragma unroll
    for (int k = 0; k < 64; k++) whh2[k] = dup2(Whh[j * 64 + k]);

    const int r = j >> 6;
    const int k = j & 63;
    float c_state = 0.0f;
    float hn      = 0.0f;
    const int dof = dir ? 64 : 0;

    if (j < 64) h_pp[j] = make_ulonglong2(0ULL, 0ULL);
    __syncthreads();

    const float* wrow = ws + j * WPAD;

    for (int s = 0; s < T; s++) {
        const int t = dir ? (T - 1 - s) : s;

        // ---- phase 0: load y0[t] for 4 rows, pair-interleaved ----
        {
            const int p  = j >> 7;            // pair 0 or 1
            const int kk = j & 127;           // feature index
            const float* yr = g_y0 + ((size_t)(b0 + 2 * p)) * (T * 128) + (size_t)t * 128;
            float va = yr[kk];
            float vb = yr[(size_t)(T * 128) + kk];
            ((ULL*)&y_pp[kk])[p] = pk2(va, vb);
        }
        __syncthreads();   // y ready, h(prev) ready, g_s free

        // ---- phase 1: g = bias + Wih1*y0 (K=128) + Whh1*h (K=64) ----
        ULL a0 = bias2, a1 = bias2, a0b = 0ULL, a1b = 0ULL;
        #pragma unroll 8
        for (int kk = 0; kk < 128; kk += 4) {
            float4 w4 = *(const float4*)(wrow + kk);
            ULL w0 = dup2(w4.x), w1 = dup2(w4.y), w2 = dup2(w4.z), w3 = dup2(w4.w);
            ulonglong2 yv0 = y_pp[kk];
            ulonglong2 yv1 = y_pp[kk + 1];
            ulonglong2 yv2 = y_pp[kk + 2];
            ulonglong2 yv3 = y_pp[kk + 3];
            fma2(a0,  w0, yv0.x);  fma2(a1,  w0, yv0.y);
            fma2(a0b, w1, yv1.x);  fma2(a1b, w1, yv1.y);
            fma2(a0,  w2, yv2.x);  fma2(a1,  w2, yv2.y);
            fma2(a0b, w3, yv3.x);  fma2(a1b, w3, yv3.y);
        }
        #pragma unroll
        for (int kk = 0; kk < 64; kk += 2) {
            ulonglong2 h0 = h_pp[kk];
            ulonglong2 h1 = h_pp[kk + 1];
            fma2(a0,  whh2[kk],     h0.x);
            fma2(a1,  whh2[kk],     h0.y);
            fma2(a0b, whh2[kk + 1], h1.x);
            fma2(a1b, whh2[kk + 1], h1.y);
        }
        add2(a0, a0b);
        add2(a1, a1b);

        float v0, v1, v2, v3;
        unpk(a0, v0, v1);
        unpk(a1, v2, v3);
        if ((j >> 6) == 2) {
            v0 = tanh_f(v0); v1 = tanh_f(v1); v2 = tanh_f(v2); v3 = tanh_f(v3);
        } else {
            v0 = sig_f(v0);  v1 = sig_f(v1);  v2 = sig_f(v2);  v3 = sig_f(v3);
        }
        g_s[0][j] = v0; g_s[1][j] = v1; g_s[2][j] = v2; g_s[3][j] = v3;
        __syncthreads();

        // ---- phase 2: state update ----
        float ig = g_s[r][k];
        float fg = g_s[r][64 + k];
        float gg = g_s[r][128 + k];
        float og = g_s[r][192 + k];
        c_state = fg * c_state + ig * gg;
        hn = og * tanh_f(c_state);
        ((float*)&h_pp[k])[r] = hn;
        // no per-step global write; only hT matters for layer 1
    }

    // final hidden state
    g_hcat[(size_t)(b0 + r) * 128 + dof + k] = hn;
}

// ---------------------------------------------------------------------------
// Kernel 3: FC head.  block = 256 = 4 rows x 64 fc1-outputs, grid = B/4.
// ---------------------------------------------------------------------------
__global__ void __launch_bounds__(256) head_kernel(
    const float* __restrict__ fc1W, const float* __restrict__ fc1b,
    const float* __restrict__ fc2W, const float* __restrict__ fc2b,
    float* __restrict__ out)
{
    __shared__ float f1[4][64];
    const int j = threadIdx.x;
    const int r = j >> 6;
    const int o = j & 63;
    const int b = blockIdx.x * 4 + r;

    const float* h = g_hcat + (size_t)b * 128;
    const float* w = fc1W + o * 128;
    float acc = fc1b[o];
    #pragma unroll 8
    for (int kk = 0; kk < 128; kk++) acc += w[kk] * h[kk];
    f1[r][o] = fmaxf(acc, 0.0f);
    __syncthreads();

    if (o < 2) {
        float a = fc2b[o];
        const float* w2 = fc2W + o * 64;
        #pragma unroll 8
        for (int kk = 0; kk < 64; kk++) a += w2[kk] * f1[r][kk];
        out[(size_t)b * 2 + o] = a;
    }
}

// ---------------------------------------------------------------------------
// Launcher
// Input order: 0 x | 1-4 Wih/Whh/bih/bhh l0_f | 5-8 l0_b | 9-12 l1_f |
//              13-16 l1_b | 17 fc1_W 18 fc1_b 19 fc2_W 20 fc2_b
// ---------------------------------------------------------------------------
extern "C" void kernel_launch(void* const* d_in, const int* in_sizes, int n_in,
                              void* d_out, int out_size)
{
    const float* x      = (const float*)d_in[0];
    const float* Wih0f  = (const float*)d_in[1];
    const float* Whh0f  = (const float*)d_in[2];
    const float* bih0f  = (const float*)d_in[3];
    const float* bhh0f  = (const float*)d_in[4];
    const float* Wih0b  = (const float*)d_in[5];
    const float* Whh0b  = (const float*)d_in[6];
    const float* bih0b  = (const float*)d_in[7];
    const float* bhh0b  = (const float*)d_in[8];
    const float* Wih1f  = (const float*)d_in[9];
    const float* Whh1f  = (const float*)d_in[10];
    const float* bih1f  = (const float*)d_in[11];
    const float* bhh1f  = (const float*)d_in[12];
    const float* Wih1b  = (const float*)d_in[13];
    const float* Whh1b  = (const float*)d_in[14];
    const float* bih1b  = (const float*)d_in[15];
    const float* bhh1b  = (const float*)d_in[16];
    const float* fc1W   = (const float*)d_in[17];
    const float* fc1b   = (const float*)d_in[18];
    const float* fc2W   = (const float*)d_in[19];
    const float* fc2b   = (const float*)d_in[20];
    float* out = (float*)d_out;

    cudaFuncSetAttribute(lstm1_kernel,
                         cudaFuncAttributeMaxDynamicSharedMemorySize, SMEM1);

    dim3 grid0(B / NB, 2);
    lstm0_kernel<<<grid0, 256>>>(x,
                                 Wih0f, Whh0f, bih0f, bhh0f,
                                 Wih0b, Whh0b, bih0b, bhh0b);

    dim3 grid1(B / NB, 2);
    lstm1_kernel<<<grid1, 256, SMEM1>>>(Wih1f, Whh1f, bih1f, bhh1f,
                                        Wih1b, Whh1b, bih1b, bhh1b);

    head_kernel<<<B / 4, 256>>>(fc1W, fc1b, fc2W, fc2b, out);
}

// round 7
// speedup vs baseline: 1.1039x; 1.1039x over previous
#include <cuda_runtime.h>
#include <cuda_bf16.h>
#include <cstdint>

#define ULL unsigned long long

// ---------------------------------------------------------------------------
// Packed f32x2 helpers. Weight pairs come straight out of LDS.128 (two gates
// per ULL, no movs); activations are stored pre-duplicated {v,v} in shared.
// ---------------------------------------------------------------------------
__device__ __forceinline__ ULL dup2(float v) {
    ULL r; asm("mov.b64 %0, {%1, %1};" : "=l"(r) : "f"(v)); return r;
}
__device__ __forceinline__ ULL pk2(float lo, float hi) {
    ULL r; asm("mov.b64 %0, {%1, %2};" : "=l"(r) : "f"(lo), "f"(hi)); return r;
}
__device__ __forceinline__ void fma2(ULL& d, ULL a, ULL b) {
    asm("fma.rn.f32x2 %0, %1, %2, %0;" : "+l"(d) : "l"(a), "l"(b));
}
__device__ __forceinline__ void unpk(ULL v, float& lo, float& hi) {
    asm("mov.b64 {%0, %1}, %2;" : "=f"(lo), "=f"(hi) : "l"(v));
}

__device__ __forceinline__ float sig_f(float x) {
    return __fdividef(1.0f, 1.0f + __expf(-x));
}
__device__ __forceinline__ float tanh_f(float x) {
    return __fdividef(2.0f, 1.0f + __expf(-2.0f * x)) - 1.0f;
}

// ---------------------------------------------------------------------------
// Problem constants
// ---------------------------------------------------------------------------
static constexpr int B  = 1024;
static constexpr int T  = 512;
static constexpr int NB = 8;        // batch rows per CTA (4 pair-groups x 2)
static constexpr int WPAD = 260;    // padded transposed-weight row (floats)

// Scratch (static device arrays: allocation-free per harness rules)
__device__ float g_y0[(size_t)B * T * 128];   // layer-0 output [b][t][dir*64+k]
__device__ float g_hcat[(size_t)B * 128];     // final hidden [hT_f, hT_b]

// ---------------------------------------------------------------------------
// Kernel 1: layer-0 bidirectional LSTM.
// grid=(B/NB, 2), block=256, 2 CTAs/SM. Thread (j=tid&63, pg=tid>>6) owns
// hidden unit j (all 4 gates) for batch rows 2pg, 2pg+1.
// Whh transposed in shared as wt[kk][j*4+gate]; h dup-packed in shared.
// ---------------------------------------------------------------------------
__global__ void __launch_bounds__(256, 2) lstm0_kernel(
    const float* __restrict__ x,
    const float* __restrict__ WihF, const float* __restrict__ WhhF,
    const float* __restrict__ bihF, const float* __restrict__ bhhF,
    const float* __restrict__ WihB, const float* __restrict__ WhhB,
    const float* __restrict__ bihB, const float* __restrict__ bhhB)
{
    extern __shared__ float sm[];
    float* wt  = sm;                         // 64 * WPAD floats
    ULL*   h_s = (ULL*)(sm + 64 * WPAD);     // [4 pg][64 j][2 rows] dup'd

    const int dir = blockIdx.y;
    const int b0  = blockIdx.x * NB;
    const int tid = threadIdx.x;
    const int j   = tid & 63;
    const int pg  = tid >> 6;

    const float* Wih = dir ? WihB : WihF;
    const float* Whh = dir ? WhhB : WhhF;
    const float* bih = dir ? bihB : bihF;
    const float* bhh = dir ? bhhB : bhhF;

    // Stage Whh transposed: wt[kk][j*4+g] = Whh[(g*64+j)*64+kk]
    for (int sidx = tid; sidx < 256 * 64; sidx += 256) {
        int gr = sidx >> 6, kk = sidx & 63;
        wt[kk * WPAD + (gr & 63) * 4 + (gr >> 6)] = Whh[sidx];
    }
    // Input weights (K=3) as gate-pairs in registers
    ULL wA[3], wB[3];
    #pragma unroll
    for (int c = 0; c < 3; c++) {
        wA[c] = pk2(Wih[j * 3 + c],         Wih[(64 + j) * 3 + c]);
        wB[c] = pk2(Wih[(128 + j) * 3 + c], Wih[(192 + j) * 3 + c]);
    }
    const ULL biasA = pk2(bih[j] + bhh[j],             bih[64 + j] + bhh[64 + j]);
    const ULL biasB = pk2(bih[128 + j] + bhh[128 + j], bih[192 + j] + bhh[192 + j]);

    for (int idx = tid; idx < 512; idx += 256) h_s[idx] = 0ULL;

    const int r0 = 2 * pg, r1 = 2 * pg + 1;
    const float* x0 = x + (size_t)(b0 + r0) * 1536;
    const float* x1 = x + (size_t)(b0 + r1) * 1536;
    const int dof = dir ? 64 : 0;
    float* y0a = g_y0 + (size_t)(b0 + r0) * (T * 128) + dof + j;
    float* y0b = g_y0 + (size_t)(b0 + r1) * (T * 128) + dof + j;

    float c0 = 0.0f, c1 = 0.0f;
    const ULL* hp = h_s + pg * 128;
    __syncthreads();

    for (int s = 0; s < T; s++) {
        const int t = dir ? (T - 1 - s) : s;

        // x loads issued early; consumed after the K-loop
        float xa0 = __ldg(x0 + t), xa1 = __ldg(x0 + 512 + t), xa2 = __ldg(x0 + 1024 + t);
        float xb0 = __ldg(x1 + t), xb1 = __ldg(x1 + 512 + t), xb2 = __ldg(x1 + 1024 + t);

        ULL A00 = biasA, A01 = biasB, A10 = biasA, A11 = biasB;
        #pragma unroll
        for (int kk = 0; kk < 64; kk++) {
            ulonglong2 w2 = *(const ulonglong2*)(wt + kk * WPAD + j * 4);
            ulonglong2 hv = *(const ulonglong2*)(hp + kk * 2);
            fma2(A00, w2.x, hv.x);  fma2(A01, w2.y, hv.x);
            fma2(A10, w2.x, hv.y);  fma2(A11, w2.y, hv.y);
        }
        // input contribution
        ULL xd;
        xd = dup2(xa0); fma2(A00, wA[0], xd); fma2(A01, wB[0], xd);
        xd = dup2(xa1); fma2(A00, wA[1], xd); fma2(A01, wB[1], xd);
        xd = dup2(xa2); fma2(A00, wA[2], xd); fma2(A01, wB[2], xd);
        xd = dup2(xb0); fma2(A10, wA[0], xd); fma2(A11, wB[0], xd);
        xd = dup2(xb1); fma2(A10, wA[1], xd); fma2(A11, wB[1], xd);
        xd = dup2(xb2); fma2(A10, wA[2], xd); fma2(A11, wB[2], xd);

        float ai, af, ag, ao;
        unpk(A00, ai, af); unpk(A01, ag, ao);
        c0 = sig_f(af) * c0 + sig_f(ai) * tanh_f(ag);
        float h0 = sig_f(ao) * tanh_f(c0);
        unpk(A10, ai, af); unpk(A11, ag, ao);
        c1 = sig_f(af) * c1 + sig_f(ai) * tanh_f(ag);
        float h1 = sig_f(ao) * tanh_f(c1);

        y0a[(size_t)t * 128] = h0;
        y0b[(size_t)t * 128] = h1;

        __syncthreads();   // all h_s reads of this step complete
        *(ulonglong2*)(h_s + pg * 128 + j * 2) = make_ulonglong2(dup2(h0), dup2(h1));
        __syncthreads();   // h_s(t+1) visible
    }
}

// ---------------------------------------------------------------------------
// Kernel 2: layer-1 bidirectional LSTM, input GEMM (K=128) fused.
// Combined weight panel wt[kk<128]=Wih1, wt[128+kk]=Whh1 transposed in shared
// (200 KB). y0 register-prefetched across the K-loop, stored dup-packed.
// ---------------------------------------------------------------------------
static constexpr int SMEM1 = 192 * WPAD * 4 + 1024 * 8 + 512 * 8;  // 211968

__global__ void __launch_bounds__(256, 1) lstm1_kernel(
    const float* __restrict__ WihF, const float* __restrict__ WhhF,
    const float* __restrict__ bihF, const float* __restrict__ bhhF,
    const float* __restrict__ WihB, const float* __restrict__ WhhB,
    const float* __restrict__ bihB, const float* __restrict__ bhhB)
{
    extern __shared__ float sm[];
    float* wt  = sm;                            // 192 * WPAD
    ULL*   y_s = (ULL*)(sm + 192 * WPAD);       // [4 pg][128 kk][2 rows]
    ULL*   h_s = y_s + 1024;                    // [4 pg][64 kk][2 rows]

    const int dir = blockIdx.y;
    const int b0  = blockIdx.x * NB;
    const int tid = threadIdx.x;
    const int j   = tid & 63;
    const int pg  = tid >> 6;

    const float* Wih = dir ? WihB : WihF;
    const float* Whh = dir ? WhhB : WhhF;
    const float* bih = dir ? bihB : bihF;
    const float* bhh = dir ? bhhB : bhhF;

    for (int sidx = tid; sidx < 256 * 128; sidx += 256) {
        int gr = sidx >> 7, kk = sidx & 127;
        wt[kk * WPAD + (gr & 63) * 4 + (gr >> 6)] = Wih[sidx];
    }
    for (int sidx = tid; sidx < 256 * 64; sidx += 256) {
        int gr = sidx >> 6, kk = sidx & 63;
        wt[(128 + kk) * WPAD + (gr & 63) * 4 + (gr >> 6)] = Whh[sidx];
    }
    const ULL biasA = pk2(bih[j] + bhh[j],             bih[64 + j] + bhh[64 + j]);
    const ULL biasB = pk2(bih[128 + j] + bhh[128 + j], bih[192 + j] + bhh[192 + j]);

    for (int idx = tid; idx < 512; idx += 256) h_s[idx] = 0ULL;

    // y-fill role: thread covers row frow (0..7), features fk, fk+32, fk+64, fk+96
    const int frow = tid >> 5;
    const int fk   = tid & 31;
    const float* ybase = g_y0 + (size_t)(b0 + frow) * (T * 128);
    ULL* ydst = y_s + (frow >> 1) * 256 + (frow & 1);   // + k*2

    float c0 = 0.0f, c1 = 0.0f, h0 = 0.0f, h1 = 0.0f;
    const ULL* yp = y_s + pg * 256;
    const ULL* hp = h_s + pg * 128;
    const int dof = dir ? 64 : 0;

    // prefetch first step's y0
    int t0 = dir ? T - 1 : 0;
    float p0 = ybase[(size_t)t0 * 128 + fk];
    float p1 = ybase[(size_t)t0 * 128 + fk + 32];
    float p2 = ybase[(size_t)t0 * 128 + fk + 64];
    float p3 = ybase[(size_t)t0 * 128 + fk + 96];
    __syncthreads();

    for (int s = 0; s < T; s++) {
        // store prefetched y for this step, dup-packed
        ydst[(fk)      * 2] = dup2(p0);
        ydst[(fk + 32) * 2] = dup2(p1);
        ydst[(fk + 64) * 2] = dup2(p2);
        ydst[(fk + 96) * 2] = dup2(p3);
        __syncthreads();   // y_s + h_s visible

        // prefetch next step's y0 (hidden under the K-loop)
        if (s + 1 < T) {
            int tn = dir ? (T - 2 - s) : (s + 1);
            p0 = ybase[(size_t)tn * 128 + fk];
            p1 = ybase[(size_t)tn * 128 + fk + 32];
            p2 = ybase[(size_t)tn * 128 + fk + 64];
            p3 = ybase[(size_t)tn * 128 + fk + 96];
        }

        ULL A00 = biasA, A01 = biasB, A10 = biasA, A11 = biasB;
        #pragma unroll
        for (int kk = 0; kk < 128; kk++) {
            ulonglong2 w2 = *(const ulonglong2*)(wt + kk * WPAD + j * 4);
            ulonglong2 yv = *(const ulonglong2*)(yp + kk * 2);
            fma2(A00, w2.x, yv.x);  fma2(A01, w2.y, yv.x);
            fma2(A10, w2.x, yv.y);  fma2(A11, w2.y, yv.y);
        }
        #pragma unroll
        for (int kk = 0; kk < 64; kk++) {
            ulonglong2 w2 = *(const ulonglong2*)(wt + (128 + kk) * WPAD + j * 4);
            ulonglong2 hv = *(const ulonglong2*)(hp + kk * 2);
            fma2(A00, w2.x, hv.x);  fma2(A01, w2.y, hv.x);
            fma2(A10, w2.x, hv.y);  fma2(A11, w2.y, hv.y);
        }

        float ai, af, ag, ao;
        unpk(A00, ai, af); unpk(A01, ag, ao);
        c0 = sig_f(af) * c0 + sig_f(ai) * tanh_f(ag);
        h0 = sig_f(ao) * tanh_f(c0);
        unpk(A10, ai, af); unpk(A11, ag, ao);
        c1 = sig_f(af) * c1 + sig_f(ai) * tanh_f(ag);
        h1 = sig_f(ao) * tanh_f(c1);

        __syncthreads();   // all y_s/h_s reads of this step complete
        *(ulonglong2*)(h_s + pg * 128 + j * 2) = make_ulonglong2(dup2(h0), dup2(h1));
        // next iteration's y-fill + barrier publishes both
    }

    g_hcat[(size_t)(b0 + 2 * pg)     * 128 + dof + j] = h0;
    g_hcat[(size_t)(b0 + 2 * pg + 1) * 128 + dof + j] = h1;
}

// ---------------------------------------------------------------------------
// Kernel 3: FC head. block = 256 = 4 rows x 64 fc1-outputs, grid = B/4.
// ---------------------------------------------------------------------------
__global__ void __launch_bounds__(256) head_kernel(
    const float* __restrict__ fc1W, const float* __restrict__ fc1b,
    const float* __restrict__ fc2W, const float* __restrict__ fc2b,
    float* __restrict__ out)
{
    __shared__ float f1[4][64];
    const int j = threadIdx.x;
    const int r = j >> 6;
    const int o = j & 63;
    const int b = blockIdx.x * 4 + r;

    const float* h = g_hcat + (size_t)b * 128;
    const float* w = fc1W + o * 128;
    float acc = fc1b[o];
    #pragma unroll 8
    for (int kk = 0; kk < 128; kk++) acc += w[kk] * h[kk];
    f1[r][o] = fmaxf(acc, 0.0f);
    __syncthreads();

    if (o < 2) {
        float a = fc2b[o];
        const float* w2 = fc2W + o * 64;
        #pragma unroll 8
        for (int kk = 0; kk < 64; kk++) a += w2[kk] * f1[r][kk];
        out[(size_t)b * 2 + o] = a;
    }
}

// ---------------------------------------------------------------------------
// Launcher
// ---------------------------------------------------------------------------
extern "C" void kernel_launch(void* const* d_in, const int* in_sizes, int n_in,
                              void* d_out, int out_size)
{
    const float* x      = (const float*)d_in[0];
    const float* Wih0f  = (const float*)d_in[1];
    const float* Whh0f  = (const float*)d_in[2];
    const float* bih0f  = (const float*)d_in[3];
    const float* bhh0f  = (const float*)d_in[4];
    const float* Wih0b  = (const float*)d_in[5];
    const float* Whh0b  = (const float*)d_in[6];
    const float* bih0b  = (const float*)d_in[7];
    const float* bhh0b  = (const float*)d_in[8];
    const float* Wih1f  = (const float*)d_in[9];
    const float* Whh1f  = (const float*)d_in[10];
    const float* bih1f  = (const float*)d_in[11];
    const float* bhh1f  = (const float*)d_in[12];
    const float* Wih1b  = (const float*)d_in[13];
    const float* Whh1b  = (const float*)d_in[14];
    const float* bih1b  = (const float*)d_in[15];
    const float* bhh1b  = (const float*)d_in[16];
    const float* fc1W   = (const float*)d_in[17];
    const float* fc1b   = (const float*)d_in[18];
    const float* fc2W   = (const float*)d_in[19];
    const float* fc2b   = (const float*)d_in[20];
    float* out = (float*)d_out;

    const int SMEM0 = 64 * WPAD * 4 + 512 * 8;   // 70656
    cudaFuncSetAttribute(lstm0_kernel,
                         cudaFuncAttributeMaxDynamicSharedMemorySize, SMEM0);
    cudaFuncSetAttribute(lstm1_kernel,
                         cudaFuncAttributeMaxDynamicSharedMemorySize, SMEM1);

    dim3 grid(B / NB, 2);
    lstm0_kernel<<<grid, 256, SMEM0>>>(x,
                                       Wih0f, Whh0f, bih0f, bhh0f,
                                       Wih0b, Whh0b, bih0b, bhh0b);

    lstm1_kernel<<<grid, 256, SMEM1>>>(Wih1f, Whh1f, bih1f, bhh1f,
                                       Wih1b, Whh1b, bih1b, bhh1b);

    head_kernel<<<B / 4, 256>>>(fc1W, fc1b, fc2W, fc2b, out);
}

// round 8
// speedup vs baseline: 1.4938x; 1.3532x over previous
#include <cuda_runtime.h>
#include <cuda_bf16.h>
#include <cstdint>

#define ULL unsigned long long

// ---------------------------------------------------------------------------
// Packed f32x2 helpers. Weight gate-pairs come straight out of LDS.128;
// activations stored pre-duplicated {v,v} in shared (STS by producer,
// broadcast LDS by consumers).
// ---------------------------------------------------------------------------
__device__ __forceinline__ ULL dup2(float v) {
    ULL r; asm("mov.b64 %0, {%1, %1};" : "=l"(r) : "f"(v)); return r;
}
__device__ __forceinline__ ULL pk2(float lo, float hi) {
    ULL r; asm("mov.b64 %0, {%1, %2};" : "=l"(r) : "f"(lo), "f"(hi)); return r;
}
__device__ __forceinline__ void fma2(ULL& d, ULL a, ULL b) {
    asm("fma.rn.f32x2 %0, %1, %2, %0;" : "+l"(d) : "l"(a), "l"(b));
}
__device__ __forceinline__ void unpk(ULL v, float& lo, float& hi) {
    asm("mov.b64 {%0, %1}, %2;" : "=f"(lo), "=f"(hi) : "l"(v));
}

__device__ __forceinline__ float sig_f(float x) {
    return __fdividef(1.0f, 1.0f + __expf(-x));
}
__device__ __forceinline__ float tanh_f(float x) {
    return __fdividef(2.0f, 1.0f + __expf(-2.0f * x)) - 1.0f;
}

// ---------------------------------------------------------------------------
// Problem constants
// ---------------------------------------------------------------------------
static constexpr int B = 1024;
static constexpr int T = 512;

// Scratch (static device arrays: allocation-free per harness rules)
__device__ float g_y0[(size_t)B * T * 128];   // layer-0 output [b][t][dir*64+k]
__device__ float g_hcat[(size_t)B * 128];     // final hidden [hT_f, hT_b]

// ---------------------------------------------------------------------------
// Kernel 1: layer-0 bidirectional LSTM.
// block=128: thread (j=tid&63, pg=tid>>6) owns hidden unit j (4 gates) for
// 4 batch rows (rows 4*pg .. 4*pg+3 of the CTA's 8). grid=(B/8, 2 dirs).
// Whh transposed in shared wt[kk][j*4+gate]; h dup-packed [kk][8 rows].
// ---------------------------------------------------------------------------
static constexpr int HS0 = 10;                            // h_s ULL stride per kk
static constexpr int SMEM0 = 64 * 256 * 4 + 64 * HS0 * 8; // 70656

__global__ void __launch_bounds__(128, 3) lstm0_kernel(
    const float* __restrict__ x,
    const float* __restrict__ WihF, const float* __restrict__ WhhF,
    const float* __restrict__ bihF, const float* __restrict__ bhhF,
    const float* __restrict__ WihB, const float* __restrict__ WhhB,
    const float* __restrict__ bihB, const float* __restrict__ bhhB)
{
    extern __shared__ float sm[];
    float* wt  = sm;                       // [64][256]
    ULL*   h_s = (ULL*)(sm + 64 * 256);    // [64][HS0]

    const int dir = blockIdx.y;
    const int b0  = blockIdx.x * 8;
    const int tid = threadIdx.x;
    const int j   = tid & 63;
    const int pg  = tid >> 6;              // 0..1

    const float* Wih = dir ? WihB : WihF;
    const float* Whh = dir ? WhhB : WhhF;
    const float* bih = dir ? bihB : bihF;
    const float* bhh = dir ? bhhB : bhhF;

    // stage Whh transposed: wt[kk][j*4+g] = Whh[(g*64+j)*64+kk]
    for (int sidx = tid; sidx < 256 * 64; sidx += 128) {
        int gr = sidx >> 6, kk = sidx & 63;
        wt[kk * 256 + (gr & 63) * 4 + (gr >> 6)] = Whh[sidx];
    }
    ULL wA[3], wB[3];
    #pragma unroll
    for (int c = 0; c < 3; c++) {
        wA[c] = pk2(Wih[j * 3 + c],         Wih[(64 + j) * 3 + c]);
        wB[c] = pk2(Wih[(128 + j) * 3 + c], Wih[(192 + j) * 3 + c]);
    }
    const ULL biasA = pk2(bih[j] + bhh[j],             bih[64 + j] + bhh[64 + j]);
    const ULL biasB = pk2(bih[128 + j] + bhh[128 + j], bih[192 + j] + bhh[192 + j]);

    for (int idx = tid; idx < 64 * HS0; idx += 128) h_s[idx] = 0ULL;

    const float* xr[4];
    float*       yr[4];
    const int dof = dir ? 64 : 0;
    #pragma unroll
    for (int r = 0; r < 4; r++) {
        int row = 4 * pg + r;
        xr[r] = x + (size_t)(b0 + row) * 1536;
        yr[r] = g_y0 + (size_t)(b0 + row) * (T * 128) + dof + j;
    }

    float cs[4] = {0.f, 0.f, 0.f, 0.f};
    const ULL* hp = h_s + pg * 4;
    __syncthreads();

    for (int s = 0; s < T; s++) {
        const int t = dir ? (T - 1 - s) : s;

        float xv[4][3];
        #pragma unroll
        for (int r = 0; r < 4; r++) {
            xv[r][0] = __ldg(xr[r] + t);
            xv[r][1] = __ldg(xr[r] + 512 + t);
            xv[r][2] = __ldg(xr[r] + 1024 + t);
        }

        ULL A0[4], A1[4];
        #pragma unroll
        for (int r = 0; r < 4; r++) { A0[r] = biasA; A1[r] = biasB; }

        #pragma unroll 8
        for (int kk = 0; kk < 64; kk++) {
            ulonglong2 w2  = *(const ulonglong2*)(wt + kk * 256 + j * 4);
            ulonglong2 hv0 = *(const ulonglong2*)(hp + kk * HS0);
            ulonglong2 hv1 = *(const ulonglong2*)(hp + kk * HS0 + 2);
            fma2(A0[0], w2.x, hv0.x);  fma2(A1[0], w2.y, hv0.x);
            fma2(A0[1], w2.x, hv0.y);  fma2(A1[1], w2.y, hv0.y);
            fma2(A0[2], w2.x, hv1.x);  fma2(A1[2], w2.y, hv1.x);
            fma2(A0[3], w2.x, hv1.y);  fma2(A1[3], w2.y, hv1.y);
        }
        #pragma unroll
        for (int r = 0; r < 4; r++) {
            #pragma unroll
            for (int c = 0; c < 3; c++) {
                ULL xd = dup2(xv[r][c]);
                fma2(A0[r], wA[c], xd);
                fma2(A1[r], wB[c], xd);
            }
        }

        float hh[4];
        #pragma unroll
        for (int r = 0; r < 4; r++) {
            float ai, af, ag, ao;
            unpk(A0[r], ai, af);
            unpk(A1[r], ag, ao);
            cs[r] = sig_f(af) * cs[r] + sig_f(ai) * tanh_f(ag);
            hh[r] = sig_f(ao) * tanh_f(cs[r]);
            yr[r][(size_t)t * 128] = hh[r];
        }

        __syncthreads();   // all h_s reads of this step complete
        *(ulonglong2*)(h_s + j * HS0 + pg * 4)     = make_ulonglong2(dup2(hh[0]), dup2(hh[1]));
        *(ulonglong2*)(h_s + j * HS0 + pg * 4 + 2) = make_ulonglong2(dup2(hh[2]), dup2(hh[3]));
        __syncthreads();   // h(t+1) visible
    }
}

// ---------------------------------------------------------------------------
// Kernel 2: layer-1 bidirectional LSTM, input GEMM (K=128) fused.
// block=256: thread (j, pg=tid>>6 in 0..3) owns hidden unit j for 4 of the
// CTA's 16 batch rows. grid=(B/16, 2) = 128 CTAs = one full wave.
// Combined weight panel wt[0..127]=Wih1^T, wt[128..191]=Whh1^T in shared.
// y0 register-prefetched across the K-loop.
// ---------------------------------------------------------------------------
static constexpr int HS1 = 18;   // h_s ULL stride per kk (pad kills write conflicts)
static constexpr int SMEM1 = 192 * 256 * 4 + 128 * 16 * 8 + 64 * HS1 * 8; // 222208

__global__ void __launch_bounds__(256, 1) lstm1_kernel(
    const float* __restrict__ WihF, const float* __restrict__ WhhF,
    const float* __restrict__ bihF, const float* __restrict__ bhhF,
    const float* __restrict__ WihB, const float* __restrict__ WhhB,
    const float* __restrict__ bihB, const float* __restrict__ bhhB)
{
    extern __shared__ float sm[];
    float* wt  = sm;                              // [192][256]
    ULL*   y_s = (ULL*)(sm + 192 * 256);          // [128 kk][16 rows]
    ULL*   h_s = y_s + 128 * 16;                  // [64 kk][HS1]

    const int dir = blockIdx.y;
    const int b0  = blockIdx.x * 16;
    const int tid = threadIdx.x;
    const int j   = tid & 63;
    const int pg  = tid >> 6;                     // 0..3

    const float* Wih = dir ? WihB : WihF;
    const float* Whh = dir ? WhhB : WhhF;
    const float* bih = dir ? bihB : bihF;
    const float* bhh = dir ? bhhB : bhhF;

    for (int sidx = tid; sidx < 256 * 128; sidx += 256) {
        int gr = sidx >> 7, kk = sidx & 127;
        wt[kk * 256 + (gr & 63) * 4 + (gr >> 6)] = Wih[sidx];
    }
    for (int sidx = tid; sidx < 256 * 64; sidx += 256) {
        int gr = sidx >> 6, kk = sidx & 63;
        wt[(128 + kk) * 256 + (gr & 63) * 4 + (gr >> 6)] = Whh[sidx];
    }
    const ULL biasA = pk2(bih[j] + bhh[j],             bih[64 + j] + bhh[64 + j]);
    const ULL biasB = pk2(bih[128 + j] + bhh[128 + j], bih[192 + j] + bhh[192 + j]);

    for (int idx = tid; idx < 64 * HS1; idx += 256) h_s[idx] = 0ULL;

    // y-fill role: thread -> (row frow, features fkgrp + 16*i, i=0..7)
    const int frow  = tid & 15;
    const int fkgrp = tid >> 4;
    const float* ybase = g_y0 + (size_t)(b0 + frow) * (T * 128);

    float cs[4] = {0.f, 0.f, 0.f, 0.f};
    float hh[4] = {0.f, 0.f, 0.f, 0.f};
    const ULL* yp = y_s + pg * 4;
    const ULL* hp = h_s + pg * 4;
    const int dof = dir ? 64 : 0;

    // prefetch first step's y0
    float p[8];
    {
        int t0 = dir ? T - 1 : 0;
        #pragma unroll
        for (int i = 0; i < 8; i++)
            p[i] = ybase[(size_t)t0 * 128 + fkgrp + 16 * i];
    }
    __syncthreads();

    for (int s = 0; s < T; s++) {
        // publish this step's y0, dup-packed
        #pragma unroll
        for (int i = 0; i < 8; i++)
            y_s[(fkgrp + 16 * i) * 16 + frow] = dup2(p[i]);
        __syncthreads();   // y_s + h_s visible

        // prefetch next step's y0 (hidden under the K-loop)
        if (s + 1 < T) {
            int tn = dir ? (T - 2 - s) : (s + 1);
            #pragma unroll
            for (int i = 0; i < 8; i++)
                p[i] = ybase[(size_t)tn * 128 + fkgrp + 16 * i];
        }

        ULL A0[4], A1[4];
        #pragma unroll
        for (int r = 0; r < 4; r++) { A0[r] = biasA; A1[r] = biasB; }

        #pragma unroll 8
        for (int kk = 0; kk < 128; kk++) {
            ulonglong2 w2  = *(const ulonglong2*)(wt + kk * 256 + j * 4);
            ulonglong2 yv0 = *(const ulonglong2*)(yp + kk * 16);
            ulonglong2 yv1 = *(const ulonglong2*)(yp + kk * 16 + 2);
            fma2(A0[0], w2.x, yv0.x);  fma2(A1[0], w2.y, yv0.x);
            fma2(A0[1], w2.x, yv0.y);  fma2(A1[1], w2.y, yv0.y);
            fma2(A0[2], w2.x, yv1.x);  fma2(A1[2], w2.y, yv1.x);
            fma2(A0[3], w2.x, yv1.y);  fma2(A1[3], w2.y, yv1.y);
        }
        #pragma unroll 8
        for (int kk = 0; kk < 64; kk++) {
            ulonglong2 w2  = *(const ulonglong2*)(wt + (128 + kk) * 256 + j * 4);
            ulonglong2 hv0 = *(const ulonglong2*)(hp + kk * HS1);
            ulonglong2 hv1 = *(const ulonglong2*)(hp + kk * HS1 + 2);
            fma2(A0[0], w2.x, hv0.x);  fma2(A1[0], w2.y, hv0.x);
            fma2(A0[1], w2.x, hv0.y);  fma2(A1[1], w2.y, hv0.y);
            fma2(A0[2], w2.x, hv1.x);  fma2(A1[2], w2.y, hv1.x);
            fma2(A0[3], w2.x, hv1.y);  fma2(A1[3], w2.y, hv1.y);
        }

        #pragma unroll
        for (int r = 0; r < 4; r++) {
            float ai, af, ag, ao;
            unpk(A0[r], ai, af);
            unpk(A1[r], ag, ao);
            cs[r] = sig_f(af) * cs[r] + sig_f(ai) * tanh_f(ag);
            hh[r] = sig_f(ao) * tanh_f(cs[r]);
        }

        __syncthreads();   // all y_s/h_s reads of this step complete
        *(ulonglong2*)(h_s + j * HS1 + pg * 4)     = make_ulonglong2(dup2(hh[0]), dup2(hh[1]));
        *(ulonglong2*)(h_s + j * HS1 + pg * 4 + 2) = make_ulonglong2(dup2(hh[2]), dup2(hh[3]));
        // next iteration's y publish + barrier makes both visible
    }

    #pragma unroll
    for (int r = 0; r < 4; r++)
        g_hcat[(size_t)(b0 + 4 * pg + r) * 128 + dof + j] = hh[r];
}

// ---------------------------------------------------------------------------
// Kernel 3: FC head. block = 256 = 4 rows x 64 fc1-outputs, grid = B/4.
// ---------------------------------------------------------------------------
__global__ void __launch_bounds__(256) head_kernel(
    const float* __restrict__ fc1W, const float* __restrict__ fc1b,
    const float* __restrict__ fc2W, const float* __restrict__ fc2b,
    float* __restrict__ out)
{
    __shared__ float f1[4][64];
    const int j = threadIdx.x;
    const int r = j >> 6;
    const int o = j & 63;
    const int b = blockIdx.x * 4 + r;

    const float* h = g_hcat + (size_t)b * 128;
    const float* w = fc1W + o * 128;
    float acc = fc1b[o];
    #pragma unroll 8
    for (int kk = 0; kk < 128; kk++) acc += w[kk] * h[kk];
    f1[r][o] = fmaxf(acc, 0.0f);
    __syncthreads();

    if (o < 2) {
        float a = fc2b[o];
        const float* w2 = fc2W + o * 64;
        #pragma unroll 8
        for (int kk = 0; kk < 64; kk++) a += w2[kk] * f1[r][kk];
        out[(size_t)b * 2 + o] = a;
    }
}

// ---------------------------------------------------------------------------
// Launcher
// ---------------------------------------------------------------------------
extern "C" void kernel_launch(void* const* d_in, const int* in_sizes, int n_in,
                              void* d_out, int out_size)
{
    const float* x      = (const float*)d_in[0];
    const float* Wih0f  = (const float*)d_in[1];
    const float* Whh0f  = (const float*)d_in[2];
    const float* bih0f  = (const float*)d_in[3];
    const float* bhh0f  = (const float*)d_in[4];
    const float* Wih0b  = (const float*)d_in[5];
    const float* Whh0b  = (const float*)d_in[6];
    const float* bih0b  = (const float*)d_in[7];
    const float* bhh0b  = (const float*)d_in[8];
    const float* Wih1f  = (const float*)d_in[9];
    const float* Whh1f  = (const float*)d_in[10];
    const float* bih1f  = (const float*)d_in[11];
    const float* bhh1f  = (const float*)d_in[12];
    const float* Wih1b  = (const float*)d_in[13];
    const float* Whh1b  = (const float*)d_in[14];
    const float* bih1b  = (const float*)d_in[15];
    const float* bhh1b  = (const float*)d_in[16];
    const float* fc1W   = (const float*)d_in[17];
    const float* fc1b   = (const float*)d_in[18];
    const float* fc2W   = (const float*)d_in[19];
    const float* fc2b   = (const float*)d_in[20];
    float* out = (float*)d_out;

    cudaFuncSetAttribute(lstm0_kernel,
                         cudaFuncAttributeMaxDynamicSharedMemorySize, SMEM0);
    cudaFuncSetAttribute(lstm1_kernel,
                         cudaFuncAttributeMaxDynamicSharedMemorySize, SMEM1);

    dim3 grid0(B / 8, 2);
    lstm0_kernel<<<grid0, 128, SMEM0>>>(x,
                                        Wih0f, Whh0f, bih0f, bhh0f,
                                        Wih0b, Whh0b, bih0b, bhh0b);

    dim3 grid1(B / 16, 2);
    lstm1_kernel<<<grid1, 256, SMEM1>>>(Wih1f, Whh1f, bih1f, bhh1f,
                                        Wih1b, Whh1b, bih1b, bhh1b);

    head_kernel<<<B / 4, 256>>>(fc1W, fc1b, fc2W, fc2b, out);
}

// round 9
// speedup vs baseline: 1.6554x; 1.1082x over previous
#include <cuda_runtime.h>
#include <cuda_bf16.h>
#include <cstdint>

#define ULL unsigned long long

// ---------------------------------------------------------------------------
// Packed f32x2 helpers. Weight gate-pairs come straight out of LDS.128;
// activations stored pre-duplicated {v,v} in shared (STS by producer,
// broadcast LDS by consumers).
// ---------------------------------------------------------------------------
__device__ __forceinline__ ULL dup2(float v) {
    ULL r; asm("mov.b64 %0, {%1, %1};" : "=l"(r) : "f"(v)); return r;
}
__device__ __forceinline__ ULL pk2(float lo, float hi) {
    ULL r; asm("mov.b64 %0, {%1, %2};" : "=l"(r) : "f"(lo), "f"(hi)); return r;
}
__device__ __forceinline__ void fma2(ULL& d, ULL a, ULL b) {
    asm("fma.rn.f32x2 %0, %1, %2, %0;" : "+l"(d) : "l"(a), "l"(b));
}
__device__ __forceinline__ void unpk(ULL v, float& lo, float& hi) {
    asm("mov.b64 {%0, %1}, %2;" : "=f"(lo), "=f"(hi) : "l"(v));
}

__device__ __forceinline__ float sig_f(float x) {
    return __fdividef(1.0f, 1.0f + __expf(-x));
}
__device__ __forceinline__ float tanh_f(float x) {
    return __fdividef(2.0f, 1.0f + __expf(-2.0f * x)) - 1.0f;
}

// ---------------------------------------------------------------------------
// Problem constants
// ---------------------------------------------------------------------------
static constexpr int B = 1024;
static constexpr int T = 512;

// Scratch (static device arrays: allocation-free per harness rules)
__device__ float g_y0[(size_t)B * T * 128];   // layer-0 output [b][t][dir*64+k]
__device__ float g_hcat[(size_t)B * 128];     // final hidden [hT_f, hT_b]

// Activation-row stride in ULLs: 18 -> 144B. 16B-aligned slots (9kk+4pg),
// conflict-free broadcast reads, <=4-way on the rare publish stores.
static constexpr int AS = 18;

// ---------------------------------------------------------------------------
// Kernel 1: layer-0 bidirectional LSTM.
// block=128: thread (j=tid&63, pg=tid>>6) owns hidden unit j (4 gates) for
// 8 batch rows (rows 8*pg .. 8*pg+7 of the CTA's 16). grid=(B/16, 2 dirs).
// Whh transposed in shared wt[kk][j*4+gate]; h dup-packed [kk][16 rows].
// ---------------------------------------------------------------------------
static constexpr int SMEM0 = 64 * 256 * 4 + 64 * AS * 8;   // 74752

__global__ void __launch_bounds__(128, 1) lstm0_kernel(
    const float* __restrict__ x,
    const float* __restrict__ WihF, const float* __restrict__ WhhF,
    const float* __restrict__ bihF, const float* __restrict__ bhhF,
    const float* __restrict__ WihB, const float* __restrict__ WhhB,
    const float* __restrict__ bihB, const float* __restrict__ bhhB)
{
    extern __shared__ float sm[];
    float* wt  = sm;                       // [64][256]
    ULL*   h_s = (ULL*)(sm + 64 * 256);    // [64][AS]

    const int dir = blockIdx.y;
    const int b0  = blockIdx.x * 16;
    const int tid = threadIdx.x;
    const int j   = tid & 63;
    const int pg  = tid >> 6;              // 0..1

    const float* Wih = dir ? WihB : WihF;
    const float* Whh = dir ? WhhB : WhhF;
    const float* bih = dir ? bihB : bihF;
    const float* bhh = dir ? bhhB : bhhF;

    // stage Whh transposed: wt[kk][j*4+g] = Whh[(g*64+j)*64+kk]
    for (int sidx = tid; sidx < 256 * 64; sidx += 128) {
        int gr = sidx >> 6, kk = sidx & 63;
        wt[kk * 256 + (gr & 63) * 4 + (gr >> 6)] = Whh[sidx];
    }
    ULL wA[3], wB[3];
    #pragma unroll
    for (int c = 0; c < 3; c++) {
        wA[c] = pk2(Wih[j * 3 + c],         Wih[(64 + j) * 3 + c]);
        wB[c] = pk2(Wih[(128 + j) * 3 + c], Wih[(192 + j) * 3 + c]);
    }
    const ULL biasA = pk2(bih[j] + bhh[j],             bih[64 + j] + bhh[64 + j]);
    const ULL biasB = pk2(bih[128 + j] + bhh[128 + j], bih[192 + j] + bhh[192 + j]);

    for (int idx = tid; idx < 64 * AS; idx += 128) h_s[idx] = 0ULL;

    const float* xr[8];
    float*       yr[8];
    const int dof = dir ? 64 : 0;
    #pragma unroll
    for (int r = 0; r < 8; r++) {
        int row = 8 * pg + r;
        xr[r] = x + (size_t)(b0 + row) * 1536;
        yr[r] = g_y0 + (size_t)(b0 + row) * (T * 128) + dof + j;
    }

    float cs[8];
    #pragma unroll
    for (int r = 0; r < 8; r++) cs[r] = 0.0f;
    const ULL* hp = h_s + pg * 8;
    __syncthreads();

    for (int s = 0; s < T; s++) {
        const int t = dir ? (T - 1 - s) : s;

        // x loads issued early; consumed after the K-loop
        float xv[8][3];
        #pragma unroll
        for (int r = 0; r < 8; r++) {
            xv[r][0] = __ldg(xr[r] + t);
            xv[r][1] = __ldg(xr[r] + 512 + t);
            xv[r][2] = __ldg(xr[r] + 1024 + t);
        }

        ULL A0[8], A1[8];
        #pragma unroll
        for (int r = 0; r < 8; r++) { A0[r] = biasA; A1[r] = biasB; }

        #pragma unroll 8
        for (int kk = 0; kk < 64; kk++) {
            ulonglong2 w2  = *(const ulonglong2*)(wt + kk * 256 + j * 4);
            ulonglong2 hv0 = *(const ulonglong2*)(hp + kk * AS);
            ulonglong2 hv1 = *(const ulonglong2*)(hp + kk * AS + 2);
            ulonglong2 hv2 = *(const ulonglong2*)(hp + kk * AS + 4);
            ulonglong2 hv3 = *(const ulonglong2*)(hp + kk * AS + 6);
            fma2(A0[0], w2.x, hv0.x);  fma2(A1[0], w2.y, hv0.x);
            fma2(A0[1], w2.x, hv0.y);  fma2(A1[1], w2.y, hv0.y);
            fma2(A0[2], w2.x, hv1.x);  fma2(A1[2], w2.y, hv1.x);
            fma2(A0[3], w2.x, hv1.y);  fma2(A1[3], w2.y, hv1.y);
            fma2(A0[4], w2.x, hv2.x);  fma2(A1[4], w2.y, hv2.x);
            fma2(A0[5], w2.x, hv2.y);  fma2(A1[5], w2.y, hv2.y);
            fma2(A0[6], w2.x, hv3.x);  fma2(A1[6], w2.y, hv3.x);
            fma2(A0[7], w2.x, hv3.y);  fma2(A1[7], w2.y, hv3.y);
        }
        #pragma unroll
        for (int r = 0; r < 8; r++) {
            #pragma unroll
            for (int c = 0; c < 3; c++) {
                ULL xd = dup2(xv[r][c]);
                fma2(A0[r], wA[c], xd);
                fma2(A1[r], wB[c], xd);
            }
        }

        float hh[8];
        #pragma unroll
        for (int r = 0; r < 8; r++) {
            float ai, af, ag, ao;
            unpk(A0[r], ai, af);
            unpk(A1[r], ag, ao);
            cs[r] = sig_f(af) * cs[r] + sig_f(ai) * tanh_f(ag);
            hh[r] = sig_f(ao) * tanh_f(cs[r]);
            yr[r][(size_t)t * 128] = hh[r];
        }

        __syncthreads();   // all h_s reads of this step complete
        {
            ULL* hw = h_s + j * AS + pg * 8;
            *(ulonglong2*)(hw)     = make_ulonglong2(dup2(hh[0]), dup2(hh[1]));
            *(ulonglong2*)(hw + 2) = make_ulonglong2(dup2(hh[2]), dup2(hh[3]));
            *(ulonglong2*)(hw + 4) = make_ulonglong2(dup2(hh[4]), dup2(hh[5]));
            *(ulonglong2*)(hw + 6) = make_ulonglong2(dup2(hh[6]), dup2(hh[7]));
        }
        __syncthreads();   // h(t+1) visible
    }
}

// ---------------------------------------------------------------------------
// Kernel 2: layer-1 bidirectional LSTM, input GEMM (K=128) fused.
// block=128: thread (j, pg) owns hidden unit j for 8 of the CTA's 16 rows.
// grid=(B/16, 2) = 128 CTAs. Combined weight panel wt[0..127]=Wih1^T,
// wt[128..191]=Whh1^T in shared (192 KB). y0 register-prefetched.
// ---------------------------------------------------------------------------
static constexpr int SMEM1 = 192 * 256 * 4 + 128 * AS * 8 + 64 * AS * 8; // 224256

__global__ void __launch_bounds__(128, 1) lstm1_kernel(
    const float* __restrict__ WihF, const float* __restrict__ WhhF,
    const float* __restrict__ bihF, const float* __restrict__ bhhF,
    const float* __restrict__ WihB, const float* __restrict__ WhhB,
    const float* __restrict__ bihB, const float* __restrict__ bhhB)
{
    extern __shared__ float sm[];
    float* wt  = sm;                              // [192][256]
    ULL*   y_s = (ULL*)(sm + 192 * 256);          // [128 kk][AS]
    ULL*   h_s = y_s + 128 * AS;                  // [64 kk][AS]

    const int dir = blockIdx.y;
    const int b0  = blockIdx.x * 16;
    const int tid = threadIdx.x;
    const int j   = tid & 63;
    const int pg  = tid >> 6;                     // 0..1

    const float* Wih = dir ? WihB : WihF;
    const float* Whh = dir ? WhhB : WhhF;
    const float* bih = dir ? bihB : bihF;
    const float* bhh = dir ? bhhB : bhhF;

    for (int sidx = tid; sidx < 256 * 128; sidx += 128) {
        int gr = sidx >> 7, kk = sidx & 127;
        wt[kk * 256 + (gr & 63) * 4 + (gr >> 6)] = Wih[sidx];
    }
    for (int sidx = tid; sidx < 256 * 64; sidx += 128) {
        int gr = sidx >> 6, kk = sidx & 63;
        wt[(128 + kk) * 256 + (gr & 63) * 4 + (gr >> 6)] = Whh[sidx];
    }
    const ULL biasA = pk2(bih[j] + bhh[j],             bih[64 + j] + bhh[64 + j]);
    const ULL biasB = pk2(bih[128 + j] + bhh[128 + j], bih[192 + j] + bhh[192 + j]);

    for (int idx = tid; idx < 64 * AS; idx += 128) h_s[idx] = 0ULL;

    // y-fill role: thread -> (row frow=tid>>3, feats 8i + (tid&7), i=0..15)
    // 8 consecutive lanes read 32B contiguous -> coalesced LDG.
    const int frow = tid >> 3;       // 0..15
    const int flo  = tid & 7;        // 0..7
    const float* ybase = g_y0 + (size_t)(b0 + frow) * (T * 128) + flo;

    float cs[8], hh[8];
    #pragma unroll
    for (int r = 0; r < 8; r++) { cs[r] = 0.0f; hh[r] = 0.0f; }
    const ULL* yp = y_s + pg * 8;
    const ULL* hp = h_s + pg * 8;
    const int dof = dir ? 64 : 0;

    // prefetch first step's y0
    float p[16];
    {
        int t0 = dir ? T - 1 : 0;
        #pragma unroll
        for (int i = 0; i < 16; i++)
            p[i] = ybase[(size_t)t0 * 128 + 8 * i];
    }
    __syncthreads();

    for (int s = 0; s < T; s++) {
        // publish this step's y0, dup-packed: y_s[feat*AS + frow]
        #pragma unroll
        for (int i = 0; i < 16; i++)
            y_s[(8 * i + flo) * AS + frow] = dup2(p[i]);
        __syncthreads();   // y_s + h_s visible

        // prefetch next step's y0 (hidden under the K-loop)
        if (s + 1 < T) {
            int tn = dir ? (T - 2 - s) : (s + 1);
            #pragma unroll
            for (int i = 0; i < 16; i++)
                p[i] = ybase[(size_t)tn * 128 + 8 * i];
        }

        ULL A0[8], A1[8];
        #pragma unroll
        for (int r = 0; r < 8; r++) { A0[r] = biasA; A1[r] = biasB; }

        #pragma unroll 8
        for (int kk = 0; kk < 128; kk++) {
            ulonglong2 w2  = *(const ulonglong2*)(wt + kk * 256 + j * 4);
            ulonglong2 yv0 = *(const ulonglong2*)(yp + kk * AS);
            ulonglong2 yv1 = *(const ulonglong2*)(yp + kk * AS + 2);
            ulonglong2 yv2 = *(const ulonglong2*)(yp + kk * AS + 4);
            ulonglong2 yv3 = *(const ulonglong2*)(yp + kk * AS + 6);
            fma2(A0[0], w2.x, yv0.x);  fma2(A1[0], w2.y, yv0.x);
            fma2(A0[1], w2.x, yv0.y);  fma2(A1[1], w2.y, yv0.y);
            fma2(A0[2], w2.x, yv1.x);  fma2(A1[2], w2.y, yv1.x);
            fma2(A0[3], w2.x, yv1.y);  fma2(A1[3], w2.y, yv1.y);
            fma2(A0[4], w2.x, yv2.x);  fma2(A1[4], w2.y, yv2.x);
            fma2(A0[5], w2.x, yv2.y);  fma2(A1[5], w2.y, yv2.y);
            fma2(A0[6], w2.x, yv3.x);  fma2(A1[6], w2.y, yv3.x);
            fma2(A0[7], w2.x, yv3.y);  fma2(A1[7], w2.y, yv3.y);
        }
        #pragma unroll 8
        for (int kk = 0; kk < 64; kk++) {
            ulonglong2 w2  = *(const ulonglong2*)(wt + (128 + kk) * 256 + j * 4);
            ulonglong2 hv0 = *(const ulonglong2*)(hp + kk * AS);
            ulonglong2 hv1 = *(const ulonglong2*)(hp + kk * AS + 2);
            ulonglong2 hv2 = *(const ulonglong2*)(hp + kk * AS + 4);
            ulonglong2 hv3 = *(const ulonglong2*)(hp + kk * AS + 6);
            fma2(A0[0], w2.x, hv0.x);  fma2(A1[0], w2.y, hv0.x);
            fma2(A0[1], w2.x, hv0.y);  fma2(A1[1], w2.y, hv0.y);
            fma2(A0[2], w2.x, hv1.x);  fma2(A1[2], w2.y, hv1.x);
            fma2(A0[3], w2.x, hv1.y);  fma2(A1[3], w2.y, hv1.y);
            fma2(A0[4], w2.x, hv2.x);  fma2(A1[4], w2.y, hv2.x);
            fma2(A0[5], w2.x, hv2.y);  fma2(A1[5], w2.y, hv2.y);
            fma2(A0[6], w2.x, hv3.x);  fma2(A1[6], w2.y, hv3.x);
            fma2(A0[7], w2.x, hv3.y);  fma2(A1[7], w2.y, hv3.y);
        }

        #pragma unroll
        for (int r = 0; r < 8; r++) {
            float ai, af, ag, ao;
            unpk(A0[r], ai, af);
            unpk(A1[r], ag, ao);
            cs[r] = sig_f(af) * cs[r] + sig_f(ai) * tanh_f(ag);
            hh[r] = sig_f(ao) * tanh_f(cs[r]);
        }

        __syncthreads();   // all y_s/h_s reads of this step complete
        {
            ULL* hw = h_s + j * AS + pg * 8;
            *(ulonglong2*)(hw)     = make_ulonglong2(dup2(hh[0]), dup2(hh[1]));
            *(ulonglong2*)(hw + 2) = make_ulonglong2(dup2(hh[2]), dup2(hh[3]));
            *(ulonglong2*)(hw + 4) = make_ulonglong2(dup2(hh[4]), dup2(hh[5]));
            *(ulonglong2*)(hw + 6) = make_ulonglong2(dup2(hh[6]), dup2(hh[7]));
        }
        // next iteration's y publish + barrier makes both visible
    }

    #pragma unroll
    for (int r = 0; r < 8; r++)
        g_hcat[(size_t)(b0 + 8 * pg + r) * 128 + dof + j] = hh[r];
}

// ---------------------------------------------------------------------------
// Kernel 3: FC head. block = 256 = 4 rows x 64 fc1-outputs, grid = B/4.
// ---------------------------------------------------------------------------
__global__ void __launch_bounds__(256) head_kernel(
    const float* __restrict__ fc1W, const float* __restrict__ fc1b,
    const float* __restrict__ fc2W, const float* __restrict__ fc2b,
    float* __restrict__ out)
{
    __shared__ float f1[4][64];
    const int j = threadIdx.x;
    const int r = j >> 6;
    const int o = j & 63;
    const int b = blockIdx.x * 4 + r;

    const float* h = g_hcat + (size_t)b * 128;
    const float* w = fc1W + o * 128;
    float acc = fc1b[o];
    #pragma unroll 8
    for (int kk = 0; kk < 128; kk++) acc += w[kk] * h[kk];
    f1[r][o] = fmaxf(acc, 0.0f);
    __syncthreads();

    if (o < 2) {
        float a = fc2b[o];
        const float* w2 = fc2W + o * 64;
        #pragma unroll 8
        for (int kk = 0; kk < 64; kk++) a += w2[kk] * f1[r][kk];
        out[(size_t)b * 2 + o] = a;
    }
}

// ---------------------------------------------------------------------------
// Launcher
// ---------------------------------------------------------------------------
extern "C" void kernel_launch(void* const* d_in, const int* in_sizes, int n_in,
                              void* d_out, int out_size)
{
    const float* x      = (const float*)d_in[0];
    const float* Wih0f  = (const float*)d_in[1];
    const float* Whh0f  = (const float*)d_in[2];
    const float* bih0f  = (const float*)d_in[3];
    const float* bhh0f  = (const float*)d_in[4];
    const float* Wih0b  = (const float*)d_in[5];
    const float* Whh0b  = (const float*)d_in[6];
    const float* bih0b  = (const float*)d_in[7];
    const float* bhh0b  = (const float*)d_in[8];
    const float* Wih1f  = (const float*)d_in[9];
    const float* Whh1f  = (const float*)d_in[10];
    const float* bih1f  = (const float*)d_in[11];
    const float* bhh1f  = (const float*)d_in[12];
    const float* Wih1b  = (const float*)d_in[13];
    const float* Whh1b  = (const float*)d_in[14];
    const float* bih1b  = (const float*)d_in[15];
    const float* bhh1b  = (const float*)d_in[16];
    const float* fc1W   = (const float*)d_in[17];
    const float* fc1b   = (const float*)d_in[18];
    const float* fc2W   = (const float*)d_in[19];
    const float* fc2b   = (const float*)d_in[20];
    float* out = (float*)d_out;

    cudaFuncSetAttribute(lstm0_kernel,
                         cudaFuncAttributeMaxDynamicSharedMemorySize, SMEM0);
    cudaFuncSetAttribute(lstm1_kernel,
                         cudaFuncAttributeMaxDynamicSharedMemorySize, SMEM1);

    dim3 grid(B / 16, 2);
    lstm0_kernel<<<grid, 128, SMEM0>>>(x,
                                       Wih0f, Whh0f, bih0f, bhh0f,
                                       Wih0b, Whh0b, bih0b, bhh0b);

    lstm1_kernel<<<grid, 128, SMEM1>>>(Wih1f, Whh1f, bih1f, bhh1f,
                                       Wih1b, Whh1b, bih1b, bhh1b);

    head_kernel<<<B / 4, 256>>>(fc1W, fc1b, fc2W, fc2b, out);
}